// round 1
// baseline (speedup 1.0000x reference)
#include <cuda_runtime.h>
#include <math.h>

#define THRV 0.6f

// Scratch (static device globals — no runtime allocation)
__device__ float g_E[16384 * 3072];       // [B][3][1024] stacked embeddings
__device__ float g_H[16384 * 300];        // MLP hidden, reused 3x
__device__ float g_common[16384 * 1024];  // common feature
__device__ float g_cat[16384 * 2048];     // [weighted_fp_sum | enhanced_common]

// ---------------------------------------------------------------------------
// Tiled SGEMM: C[M,N] = epi(A[M,K] @ W[K,N] + bias)
//   EPI 0: bias          EPI 1: relu(bias)          EPI 2: X * sigmoid(bias)
// BM=128, BN=64, BK=16, 256 threads, 8x4 per thread.
// ---------------------------------------------------------------------------
template <int EPI>
__global__ __launch_bounds__(256) void sgemm(
    const float* __restrict__ A, const float* __restrict__ W,
    const float* __restrict__ bias, float* __restrict__ C,
    int M, int N, int K, int lda, int ldc,
    const float* __restrict__ X, int ldx)
{
    __shared__ float As[16][132];
    __shared__ float Bs[16][68];

    const int tid = threadIdx.x;
    const int tx = tid & 15;   // N direction (x4)
    const int ty = tid >> 4;   // M direction (x8)
    const int rowBase = blockIdx.y * 128;
    const int colBase = blockIdx.x * 64;

    float acc[8][4];
#pragma unroll
    for (int i = 0; i < 8; i++)
#pragma unroll
        for (int j = 0; j < 4; j++) acc[i][j] = 0.f;

    const int la_k = tid & 15;   // k within A tile
    const int la_m = tid >> 4;   // m base (stride 16)
    const int lb_n = tid & 63;   // n within B tile
    const int lb_k = tid >> 6;   // k base (stride 4)

    for (int k0 = 0; k0 < K; k0 += 16) {
#pragma unroll
        for (int t = 0; t < 8; t++) {
            int m = la_m + 16 * t;
            int k = k0 + la_k;
            As[la_k][m] = (k < K) ? A[(size_t)(rowBase + m) * lda + k] : 0.f;
        }
#pragma unroll
        for (int t = 0; t < 4; t++) {
            int k = k0 + lb_k + 4 * t;
            int n = colBase + lb_n;
            Bs[lb_k + 4 * t][lb_n] = (k < K && n < N) ? W[(size_t)k * N + n] : 0.f;
        }
        __syncthreads();
#pragma unroll
        for (int kk = 0; kk < 16; kk++) {
            float4 a0 = *reinterpret_cast<const float4*>(&As[kk][ty * 8]);
            float4 a1 = *reinterpret_cast<const float4*>(&As[kk][ty * 8 + 4]);
            float4 bv = *reinterpret_cast<const float4*>(&Bs[kk][tx * 4]);
            float a[8] = {a0.x, a0.y, a0.z, a0.w, a1.x, a1.y, a1.z, a1.w};
            float bb[4] = {bv.x, bv.y, bv.z, bv.w};
#pragma unroll
            for (int i = 0; i < 8; i++)
#pragma unroll
                for (int j = 0; j < 4; j++) acc[i][j] += a[i] * bb[j];
        }
        __syncthreads();
    }

#pragma unroll
    for (int i = 0; i < 8; i++) {
        int row = rowBase + ty * 8 + i;
        if (row >= M) continue;
#pragma unroll
        for (int j = 0; j < 4; j++) {
            int col = colBase + tx * 4 + j;
            if (col < N) {
                float v = acc[i][j] + (bias ? bias[col] : 0.f);
                if (EPI == 1) v = v > 0.f ? v : 0.f;
                if (EPI == 2) {
                    float s = 1.f / (1.f + expf(-v));
                    v = X[(size_t)row * ldx + col] * s;
                }
                C[(size_t)row * ldc + col] = v;
            }
        }
    }
}

// ---------------------------------------------------------------------------
// Per-row fusion: norms, pair similarities, keep-masked softmax, elementwise
// masked common feature, gate-softmax weighted sum.
// One block per row (B=16384), 256 threads.
// ---------------------------------------------------------------------------
__global__ __launch_bounds__(256) void rowfuse(
    const float* __restrict__ E, const float* __restrict__ wgW,
    const float* __restrict__ wgb,
    float* __restrict__ common, float* __restrict__ cat)
{
    __shared__ float sE[3072];
    __shared__ float sred[8][9];
    __shared__ float sc[10];

    const int b = blockIdx.x;
    const int tid = threadIdx.x;
    const float* Erow = E + (size_t)b * 3072;
    for (int i = tid; i < 3072; i += 256) sE[i] = Erow[i];
    __syncthreads();

    float r[9] = {0, 0, 0, 0, 0, 0, 0, 0, 0};
    for (int h = tid; h < 1024; h += 256) {
        float e0 = sE[h], e1 = sE[1024 + h], e2 = sE[2048 + h];
        r[0] += e0 * e0; r[1] += e1 * e1; r[2] += e2 * e2;
        r[3] += e0 * e1; r[4] += e0 * e2; r[5] += e1 * e2;
    }
    for (int j = tid; j < 3072; j += 256) {
        float v = sE[j];
        r[6] += v * wgW[3 * j + 0];
        r[7] += v * wgW[3 * j + 1];
        r[8] += v * wgW[3 * j + 2];
    }
#pragma unroll
    for (int q = 0; q < 9; q++)
#pragma unroll
        for (int o = 16; o > 0; o >>= 1) r[q] += __shfl_down_sync(0xffffffffu, r[q], o);

    int warp = tid >> 5, lane = tid & 31;
    if (lane == 0)
        for (int q = 0; q < 9; q++) sred[warp][q] = r[q];
    __syncthreads();

    if (tid == 0) {
        float s[9];
        for (int q = 0; q < 9; q++) {
            float a = 0.f;
            for (int w2 = 0; w2 < 8; w2++) a += sred[w2][q];
            s[q] = a;
        }
        float inv0 = 1.f / fmaxf(sqrtf(s[0]), 1e-12f);
        float inv1 = 1.f / fmaxf(sqrtf(s[1]), 1e-12f);
        float inv2 = 1.f / fmaxf(sqrtf(s[2]), 1e-12f);
        float sim0 = s[3] * inv0 * inv1;
        float sim1 = s[4] * inv0 * inv2;
        float sim2 = s[5] * inv1 * inv2;
        bool k0 = sim0 > THRV, k1 = sim1 > THRV, k2 = sim2 > THRV;
        float x0 = k0 ? sim0 : -1e9f;
        float x1 = k1 ? sim1 : -1e9f;
        float x2 = k2 ? sim2 : -1e9f;
        float mx = fmaxf(x0, fmaxf(x1, x2));
        float ex0 = expf(x0 - mx), ex1 = expf(x1 - mx), ex2 = expf(x2 - mx);
        float es = ex0 + ex1 + ex2;
        float l0 = s[6] + wgb[0], l1 = s[7] + wgb[1], l2 = s[8] + wgb[2];
        float lm = fmaxf(l0, fmaxf(l1, l2));
        float g0 = expf(l0 - lm), g1 = expf(l1 - lm), g2 = expf(l2 - lm);
        float gs = g0 + g1 + g2;
        sc[0] = inv0; sc[1] = inv1; sc[2] = inv2;
        sc[3] = ex0 / es; sc[4] = ex1 / es; sc[5] = ex2 / es;
        sc[6] = g0 / gs; sc[7] = g1 / gs; sc[8] = g2 / gs;
        sc[9] = (k0 || k1 || k2) ? 1.f : 0.f;
    }
    __syncthreads();

    float inv0 = sc[0], inv1 = sc[1], inv2 = sc[2];
    float w0 = sc[3], w1 = sc[4], w2 = sc[5];
    float f0 = sc[6], f1 = sc[7], f2 = sc[8];
    bool any = sc[9] > 0.5f;
    float* crow = common + (size_t)b * 1024;
    float* catrow = cat + (size_t)b * 2048;
    for (int h = tid; h < 1024; h += 256) {
        float e0 = sE[h], e1 = sE[1024 + h], e2 = sE[2048 + h];
        float n0 = e0 * inv0, n1 = e1 * inv1, n2 = e2 * inv2;
        float wsum = 0.f;
        if (n0 * n1 > THRV) wsum += w0 * 0.5f * (e0 + e1);
        if (n0 * n2 > THRV) wsum += w1 * 0.5f * (e0 + e2);
        if (n1 * n2 > THRV) wsum += w2 * 0.5f * (e1 + e2);
        float mean = (e0 + e1 + e2) * (1.f / 3.f);
        crow[h] = any ? wsum : mean;
        catrow[h] = f0 * e0 + f1 * e1 + f2 * e2;
    }
}

// ---------------------------------------------------------------------------
extern "C" void kernel_launch(void* const* d_in, const int* in_sizes, int n_in,
                              void* d_out, int out_size)
{
    const float* brics = (const float*)d_in[0];
    const float* fg    = (const float*)d_in[1];
    const float* ph    = (const float*)d_in[2];
    const float* bw1 = (const float*)d_in[3];  const float* bb1 = (const float*)d_in[4];
    const float* bw2 = (const float*)d_in[5];  const float* bb2 = (const float*)d_in[6];
    const float* fw1 = (const float*)d_in[7];  const float* fb1 = (const float*)d_in[8];
    const float* fw2 = (const float*)d_in[9];  const float* fb2 = (const float*)d_in[10];
    const float* pw1 = (const float*)d_in[11]; const float* pb1 = (const float*)d_in[12];
    const float* pw2 = (const float*)d_in[13]; const float* pb2 = (const float*)d_in[14];
    const float* wgW = (const float*)d_in[15]; const float* wgb = (const float*)d_in[16];
    const float* enhW = (const float*)d_in[17]; const float* enhb = (const float*)d_in[18];
    const float* fusW = (const float*)d_in[19]; const float* fusb = (const float*)d_in[20];
    float* out = (float*)d_out;

    float *E, *H, *C, *CAT;
    cudaGetSymbolAddress((void**)&E, g_E);
    cudaGetSymbolAddress((void**)&H, g_H);
    cudaGetSymbolAddress((void**)&C, g_common);
    cudaGetSymbolAddress((void**)&CAT, g_cat);

    const int B = 16384, Hd = 1024, D = 300;
    dim3 blk(256);
    dim3 gD((D + 63) / 64, B / 128);    // N=300
    dim3 gH((Hd + 63) / 64, B / 128);   // N=1024

    // Three branch MLPs: hidden (relu) then projection (bias), strided into g_E
    sgemm<1><<<gD, blk>>>(brics, bw1, bb1, H, B, D, Hd, Hd, D, nullptr, 0);
    sgemm<0><<<gH, blk>>>(H, bw2, bb2, E, B, Hd, D, D, 3072, nullptr, 0);
    sgemm<1><<<gD, blk>>>(fg, fw1, fb1, H, B, D, Hd, Hd, D, nullptr, 0);
    sgemm<0><<<gH, blk>>>(H, fw2, fb2, E + 1024, B, Hd, D, D, 3072, nullptr, 0);
    sgemm<1><<<gD, blk>>>(ph, pw1, pb1, H, B, D, Hd, Hd, D, nullptr, 0);
    sgemm<0><<<gH, blk>>>(H, pw2, pb2, E + 2048, B, Hd, D, D, 3072, nullptr, 0);

    // Per-row similarity fusion → common, and gate-weighted sum → cat[:, :1024]
    rowfuse<<<B, blk>>>(E, wgW, wgb, C, CAT);

    // enhanced_common = common * sigmoid(common @ enhW + enhb) → cat[:, 1024:]
    sgemm<2><<<gH, blk>>>(C, enhW, enhb, CAT + 1024, B, Hd, Hd, Hd, 2048, C, Hd);

    // fused = cat @ fusW + fusb
    sgemm<0><<<gH, blk>>>(CAT, fusW, fusb, out, B, Hd, 2048, 2048, Hd, nullptr, 0);
}

// round 3
// speedup vs baseline: 2.8030x; 2.8030x over previous
#include <cuda_runtime.h>
#include <math.h>
#include <stdint.h>

#define THRV 0.6f

// ---------------- scratch (device globals: no runtime allocation) ----------
__device__ float g_Xr[16384 * 1024];      // rounded input (reused per branch)
__device__ float g_H[16384 * 320];        // MLP hidden (padded N/K=320), reused
__device__ float g_E[16384 * 3072];       // [B][3][1024]
__device__ float g_C[16384 * 1024];       // common
__device__ float g_CAT[16384 * 2048];     // [weighted_fp_sum | enhanced_common]
__device__ float g_WT1[384 * 1024];       // W1^T padded
__device__ float g_WT2[1024 * 320];       // W2^T padded
__device__ float g_enhT[1024 * 1024];
__device__ float g_fusT[1024 * 2048];

// ---------------- helpers ----------------------------------------------------
__device__ __forceinline__ uint32_t smem_u32(const void* p) {
    uint32_t a;
    asm("{ .reg .u64 t; cvta.to.shared.u64 t, %1; cvt.u32.u64 %0, t; }" : "=r"(a) : "l"(p));
    return a;
}
__device__ __forceinline__ float rna_tf32(float x) {
    uint32_t u;
    asm("cvt.rna.tf32.f32 %0, %1;" : "=r"(u) : "f"(x));
    return __uint_as_float(u);
}
#define CP_ASYNC16(dst, src) asm volatile("cp.async.cg.shared.global [%0], [%1], 16;" :: "r"(dst), "l"(src))
#define CP_COMMIT()          asm volatile("cp.async.commit_group;" ::: "memory")

__device__ __forceinline__ void mma_tf32(
    float& c0, float& c1, float& c2, float& c3,
    uint32_t a0, uint32_t a1, uint32_t a2, uint32_t a3,
    uint32_t b0, uint32_t b1)
{
    asm volatile(
        "mma.sync.aligned.m16n8k8.row.col.f32.tf32.tf32.f32 "
        "{%0,%1,%2,%3}, {%4,%5,%6,%7}, {%8,%9}, {%0,%1,%2,%3};"
        : "+f"(c0), "+f"(c1), "+f"(c2), "+f"(c3)
        : "r"(a0), "r"(a1), "r"(a2), "r"(a3), "r"(b0), "r"(b1));
}

// ---------------- tf32 tensor-core GEMM --------------------------------------
// C[M,N] = epi(A[M,K] @ Bt[N,K]^T + bias).  A row-major, Bt row-major (=W^T).
// BM=128, BN=128, BK=16, 256 thr, 8 warps (2m x 4n), warp tile 64x32.
// EPI 0: bias; 1: relu(bias); 2: X*sigmoid(bias).
// K % 16 == 0; M % 128 == 0; Bt padded to >= 128*gridDim.x rows.
static constexpr int LDT = 20;  // smem row stride (floats): conflict-free for frag loads

__device__ __forceinline__ void load_tile(
    const float* __restrict__ A, int lda, int rowBase,
    const float* __restrict__ Bt, int ldb, int colBase,
    int k0, float* as, float* bs, int tid)
{
#pragma unroll
    for (int i = 0; i < 2; i++) {
        int idx = i * 256 + tid;
        int r = idx >> 2, c = (idx & 3) << 2;
        CP_ASYNC16(smem_u32(as + r * LDT + c), A + (size_t)(rowBase + r) * lda + k0 + c);
    }
#pragma unroll
    for (int i = 0; i < 2; i++) {
        int idx = i * 256 + tid;
        int r = idx >> 2, c = (idx & 3) << 2;
        CP_ASYNC16(smem_u32(bs + r * LDT + c), Bt + (size_t)(colBase + r) * ldb + k0 + c);
    }
    CP_COMMIT();
}

template <int EPI, bool ROUND>
__global__ void __launch_bounds__(256, 2) tgemm(
    const float* __restrict__ A, int lda,
    const float* __restrict__ Bt, int ldb,
    const float* __restrict__ bias,
    float* __restrict__ C, int ldc,
    int Ntrue, int Nstore, int K,
    const float* __restrict__ X, int ldx)
{
    __shared__ float As[2][128 * LDT];
    __shared__ float Bs[2][128 * LDT];

    const int tid = threadIdx.x;
    const int wid = tid >> 5, lane = tid & 31;
    const int g = lane >> 2, tig = lane & 3;
    const int warp_m = wid & 1, warp_n = wid >> 1;
    const int rowBase = blockIdx.y * 128;
    const int colBase = blockIdx.x * 128;
    const int S = K >> 4;

    float acc[4][4][4];
#pragma unroll
    for (int mt = 0; mt < 4; mt++)
#pragma unroll
        for (int nt = 0; nt < 4; nt++)
#pragma unroll
            for (int q = 0; q < 4; q++) acc[mt][nt][q] = 0.f;

    load_tile(A, lda, rowBase, Bt, ldb, colBase, 0, As[0], Bs[0], tid);
    if (S > 1) load_tile(A, lda, rowBase, Bt, ldb, colBase, 16, As[1], Bs[1], tid);

    for (int s = 0; s < S; s++) {
        const int b = s & 1;
        if (s + 1 < S) asm volatile("cp.async.wait_group 1;" ::: "memory");
        else           asm volatile("cp.async.wait_group 0;" ::: "memory");
        __syncthreads();

        const float* aw = As[b] + (warp_m * 64 + g) * LDT + tig;
        const float* bw = Bs[b] + (warp_n * 32 + g) * LDT + tig;
#pragma unroll
        for (int kk = 0; kk < 16; kk += 8) {
            uint32_t af[4][4];
#pragma unroll
            for (int mt = 0; mt < 4; mt++) {
                const float* p = aw + mt * 16 * LDT + kk;
                af[mt][0] = __float_as_uint(p[0]);
                af[mt][1] = __float_as_uint(p[8 * LDT]);
                af[mt][2] = __float_as_uint(p[4]);
                af[mt][3] = __float_as_uint(p[8 * LDT + 4]);
            }
            uint32_t bf[4][2];
#pragma unroll
            for (int nt = 0; nt < 4; nt++) {
                const float* p = bw + nt * 8 * LDT + kk;
                bf[nt][0] = __float_as_uint(p[0]);
                bf[nt][1] = __float_as_uint(p[4]);
            }
#pragma unroll
            for (int mt = 0; mt < 4; mt++)
#pragma unroll
                for (int nt = 0; nt < 4; nt++)
                    mma_tf32(acc[mt][nt][0], acc[mt][nt][1], acc[mt][nt][2], acc[mt][nt][3],
                             af[mt][0], af[mt][1], af[mt][2], af[mt][3],
                             bf[nt][0], bf[nt][1]);
        }
        __syncthreads();
        if (s + 2 < S)
            load_tile(A, lda, rowBase, Bt, ldb, colBase, (s + 2) * 16, As[b], Bs[b], tid);
    }

    // ---- epilogue: direct stores ------------------------------------------
#pragma unroll
    for (int mt = 0; mt < 4; mt++) {
#pragma unroll
        for (int nt = 0; nt < 4; nt++) {
            int col = colBase + warp_n * 32 + nt * 8 + 2 * tig;
#pragma unroll
            for (int half = 0; half < 2; half++) {
                int row = rowBase + warp_m * 64 + mt * 16 + g + half * 8;
                float v0 = acc[mt][nt][half * 2 + 0];
                float v1 = acc[mt][nt][half * 2 + 1];
#pragma unroll
                for (int q = 0; q < 2; q++) {
                    int cc = col + q;
                    if (cc >= Nstore) continue;
                    float v = 0.f;
                    if (cc < Ntrue) {
                        v = (q ? v1 : v0) + bias[cc];
                        if (EPI == 1) v = fmaxf(v, 0.f);
                        if (EPI == 2) {
                            float sg = 1.f / (1.f + expf(-v));
                            v = X[(size_t)row * ldx + cc] * sg;
                        }
                        if (ROUND) v = rna_tf32(v);
                    }
                    C[(size_t)row * ldc + cc] = v;
                }
            }
        }
    }
}

// ---------------- transpose + tf32-round weights ----------------------------
__global__ void __launch_bounds__(256) transposeW(
    const float* __restrict__ W, float* __restrict__ WT,
    int K, int N, int Kpad, int Npad)
{
    __shared__ float t[32][33];
    int kb = blockIdx.x * 32, nb = blockIdx.y * 32;
#pragma unroll
    for (int i = 0; i < 4; i++) {
        int kk = kb + threadIdx.y + i * 8, nn = nb + threadIdx.x;
        t[threadIdx.y + i * 8][threadIdx.x] = (kk < K && nn < N) ? W[(size_t)kk * N + nn] : 0.f;
    }
    __syncthreads();
#pragma unroll
    for (int i = 0; i < 4; i++) {
        int nn = nb + threadIdx.y + i * 8, kk = kb + threadIdx.x;
        if (nn < Npad && kk < Kpad)
            WT[(size_t)nn * Kpad + kk] = rna_tf32(t[threadIdx.x][threadIdx.y + i * 8]);
    }
}

__global__ void __launch_bounds__(256) roundK(const float* __restrict__ x, float* __restrict__ y, int n4) {
    int i = blockIdx.x * 256 + threadIdx.x;
    if (i < n4) {
        float4 v = reinterpret_cast<const float4*>(x)[i];
        v.x = rna_tf32(v.x); v.y = rna_tf32(v.y); v.z = rna_tf32(v.z); v.w = rna_tf32(v.w);
        reinterpret_cast<float4*>(y)[i] = v;
    }
}

// ---------------- per-row fusion --------------------------------------------
__global__ __launch_bounds__(256) void rowfuse(
    const float* __restrict__ E, const float* __restrict__ wgW,
    const float* __restrict__ wgb,
    float* __restrict__ common, float* __restrict__ cat)
{
    __shared__ float sE[3072];
    __shared__ float sred[8][9];
    __shared__ float sc[10];

    const int b = blockIdx.x;
    const int tid = threadIdx.x;
    const float* Erow = E + (size_t)b * 3072;
    for (int i = tid; i < 3072; i += 256) sE[i] = Erow[i];
    __syncthreads();

    float r[9] = {0, 0, 0, 0, 0, 0, 0, 0, 0};
    for (int h = tid; h < 1024; h += 256) {
        float e0 = sE[h], e1 = sE[1024 + h], e2 = sE[2048 + h];
        r[0] += e0 * e0; r[1] += e1 * e1; r[2] += e2 * e2;
        r[3] += e0 * e1; r[4] += e0 * e2; r[5] += e1 * e2;
    }
    for (int j = tid; j < 3072; j += 256) {
        float v = sE[j];
        r[6] += v * wgW[3 * j + 0];
        r[7] += v * wgW[3 * j + 1];
        r[8] += v * wgW[3 * j + 2];
    }
#pragma unroll
    for (int q = 0; q < 9; q++)
#pragma unroll
        for (int o = 16; o > 0; o >>= 1) r[q] += __shfl_down_sync(0xffffffffu, r[q], o);

    int warp = tid >> 5, lane = tid & 31;
    if (lane == 0)
        for (int q = 0; q < 9; q++) sred[warp][q] = r[q];
    __syncthreads();

    if (tid == 0) {
        float s[9];
        for (int q = 0; q < 9; q++) {
            float a = 0.f;
            for (int w2 = 0; w2 < 8; w2++) a += sred[w2][q];
            s[q] = a;
        }
        float inv0 = 1.f / fmaxf(sqrtf(s[0]), 1e-12f);
        float inv1 = 1.f / fmaxf(sqrtf(s[1]), 1e-12f);
        float inv2 = 1.f / fmaxf(sqrtf(s[2]), 1e-12f);
        float sim0 = s[3] * inv0 * inv1;
        float sim1 = s[4] * inv0 * inv2;
        float sim2 = s[5] * inv1 * inv2;
        bool k0 = sim0 > THRV, k1 = sim1 > THRV, k2 = sim2 > THRV;
        float x0 = k0 ? sim0 : -1e9f;
        float x1 = k1 ? sim1 : -1e9f;
        float x2 = k2 ? sim2 : -1e9f;
        float mx = fmaxf(x0, fmaxf(x1, x2));
        float ex0 = expf(x0 - mx), ex1 = expf(x1 - mx), ex2 = expf(x2 - mx);
        float es = ex0 + ex1 + ex2;
        float l0 = s[6] + wgb[0], l1 = s[7] + wgb[1], l2 = s[8] + wgb[2];
        float lm = fmaxf(l0, fmaxf(l1, l2));
        float g0 = expf(l0 - lm), g1 = expf(l1 - lm), g2 = expf(l2 - lm);
        float gs = g0 + g1 + g2;
        sc[0] = inv0; sc[1] = inv1; sc[2] = inv2;
        sc[3] = ex0 / es; sc[4] = ex1 / es; sc[5] = ex2 / es;
        sc[6] = g0 / gs; sc[7] = g1 / gs; sc[8] = g2 / gs;
        sc[9] = (k0 || k1 || k2) ? 1.f : 0.f;
    }
    __syncthreads();

    float inv0 = sc[0], inv1 = sc[1], inv2 = sc[2];
    float w0 = sc[3], w1 = sc[4], w2 = sc[5];
    float f0 = sc[6], f1 = sc[7], f2 = sc[8];
    bool any = sc[9] > 0.5f;
    float* crow = common + (size_t)b * 1024;
    float* catrow = cat + (size_t)b * 2048;
    for (int h = tid; h < 1024; h += 256) {
        float e0 = sE[h], e1 = sE[1024 + h], e2 = sE[2048 + h];
        float n0 = e0 * inv0, n1 = e1 * inv1, n2 = e2 * inv2;
        float wsum = 0.f;
        if (n0 * n1 > THRV) wsum += w0 * 0.5f * (e0 + e1);
        if (n0 * n2 > THRV) wsum += w1 * 0.5f * (e0 + e2);
        if (n1 * n2 > THRV) wsum += w2 * 0.5f * (e1 + e2);
        float mean = (e0 + e1 + e2) * (1.f / 3.f);
        crow[h] = rna_tf32(any ? wsum : mean);
        catrow[h] = rna_tf32(f0 * e0 + f1 * e1 + f2 * e2);
    }
}

// ---------------------------------------------------------------------------
extern "C" void kernel_launch(void* const* d_in, const int* in_sizes, int n_in,
                              void* d_out, int out_size)
{
    const float* xin[3] = {(const float*)d_in[0], (const float*)d_in[1], (const float*)d_in[2]};
    const float* w1[3]  = {(const float*)d_in[3], (const float*)d_in[7], (const float*)d_in[11]};
    const float* b1[3]  = {(const float*)d_in[4], (const float*)d_in[8], (const float*)d_in[12]};
    const float* w2[3]  = {(const float*)d_in[5], (const float*)d_in[9], (const float*)d_in[13]};
    const float* b2[3]  = {(const float*)d_in[6], (const float*)d_in[10], (const float*)d_in[14]};
    const float* wgW = (const float*)d_in[15]; const float* wgb = (const float*)d_in[16];
    const float* enhW = (const float*)d_in[17]; const float* enhb = (const float*)d_in[18];
    const float* fusW = (const float*)d_in[19]; const float* fusb = (const float*)d_in[20];
    float* out = (float*)d_out;

    float *Xr, *H, *E, *C, *CAT, *WT1, *WT2, *ENT, *FUT;
    cudaGetSymbolAddress((void**)&Xr, g_Xr);
    cudaGetSymbolAddress((void**)&H, g_H);
    cudaGetSymbolAddress((void**)&E, g_E);
    cudaGetSymbolAddress((void**)&C, g_C);
    cudaGetSymbolAddress((void**)&CAT, g_CAT);
    cudaGetSymbolAddress((void**)&WT1, g_WT1);
    cudaGetSymbolAddress((void**)&WT2, g_WT2);
    cudaGetSymbolAddress((void**)&ENT, g_enhT);
    cudaGetSymbolAddress((void**)&FUT, g_fusT);

    dim3 tb(32, 8);
    const int Mt = 16384 / 128;  // 128 M-tiles

    for (int br = 0; br < 3; br++) {
        // W1^T : [300->384 pad, 1024], W2^T : [1024, 300->320 pad]
        transposeW<<<dim3(32, 12), tb>>>(w1[br], WT1, 1024, 300, 1024, 384);
        transposeW<<<dim3(10, 32), tb>>>(w2[br], WT2, 300, 1024, 320, 1024);
        roundK<<<16384, 256>>>(xin[br], Xr, 16384 * 1024 / 4);
        // H = relu(X @ W1 + b1)   (N=300 true, stored padded to 320 with zeros)
        tgemm<1, true><<<dim3(3, Mt), 256>>>(Xr, 1024, WT1, 1024, b1[br],
                                             H, 320, 300, 320, 1024, nullptr, 0);
        // E[:, br, :] = H @ W2 + b2
        tgemm<0, true><<<dim3(8, Mt), 256>>>(H, 320, WT2, 320, b2[br],
                                             E + br * 1024, 3072, 1024, 1024, 320, nullptr, 0);
    }

    rowfuse<<<16384, 256>>>(E, wgW, wgb, C, CAT);

    transposeW<<<dim3(32, 32), tb>>>(enhW, ENT, 1024, 1024, 1024, 1024);
    tgemm<2, true><<<dim3(8, Mt), 256>>>(C, 1024, ENT, 1024, enhb,
                                         CAT + 1024, 2048, 1024, 1024, 1024, C, 1024);

    transposeW<<<dim3(64, 32), tb>>>(fusW, FUT, 2048, 1024, 2048, 1024);
    tgemm<0, false><<<dim3(8, Mt), 256>>>(CAT, 2048, FUT, 2048, fusb,
                                          out, 1024, 1024, 1024, 2048, nullptr, 0);
}

// round 4
// speedup vs baseline: 3.0256x; 1.0794x over previous
#include <cuda_runtime.h>
#include <math.h>
#include <stdint.h>

#define THRV 0.6f

// ---------------- scratch (device globals: no runtime allocation) ----------
__device__ float g_H[16384 * 320];        // MLP hidden (padded N/K=320), reused
__device__ float g_E[16384 * 3072];       // [B][3][1024]
__device__ float g_C[16384 * 1024];       // common
__device__ float g_CAT[16384 * 2048];     // [weighted_fp_sum | enhanced_common]
__device__ float g_WT1[384 * 1024];       // W1^T padded
__device__ float g_WT2[1024 * 320];       // W2^T padded
__device__ float g_enhT[1024 * 1024];
__device__ float g_fusT[1024 * 2048];

// ---------------- helpers ----------------------------------------------------
__device__ __forceinline__ uint32_t smem_u32(const void* p) {
    uint32_t a;
    asm("{ .reg .u64 t; cvta.to.shared.u64 t, %1; cvt.u32.u64 %0, t; }" : "=r"(a) : "l"(p));
    return a;
}
// load float from smem and round-to-nearest into tf32 bit pattern
__device__ __forceinline__ uint32_t ld_rna(const float* p) {
    uint32_t u;
    asm("cvt.rna.tf32.f32 %0, %1;" : "=r"(u) : "f"(*p));
    return u;
}
#define CP_ASYNC16(dst, src) asm volatile("cp.async.cg.shared.global [%0], [%1], 16;" :: "r"(dst), "l"(src))
#define CP_COMMIT()          asm volatile("cp.async.commit_group;" ::: "memory")

__device__ __forceinline__ void mma_tf32(
    float& c0, float& c1, float& c2, float& c3,
    uint32_t a0, uint32_t a1, uint32_t a2, uint32_t a3,
    uint32_t b0, uint32_t b1)
{
    asm volatile(
        "mma.sync.aligned.m16n8k8.row.col.f32.tf32.tf32.f32 "
        "{%0,%1,%2,%3}, {%4,%5,%6,%7}, {%8,%9}, {%0,%1,%2,%3};"
        : "+f"(c0), "+f"(c1), "+f"(c2), "+f"(c3)
        : "r"(a0), "r"(a1), "r"(a2), "r"(a3), "r"(b0), "r"(b1));
}

// ---------------- tf32 tensor-core GEMM --------------------------------------
// C[M,N] = epi(A[M,K] @ Bt[N,K]^T + bias).  A row-major, Bt row-major (=W^T).
// BM=128, BN=128, BK=16, 256 thr, 8 warps (2m x 4n), warp tile 64x32.
// 4-stage cp.async pipeline, 1 sync/slice. Frags rounded to tf32 in-register.
// EPI 0: bias; 1: relu(bias); 2: X*sigmoid(bias).
static constexpr int LDT = 20;                    // conflict-free smem stride
static constexpr int STAGE_F = 128 * LDT;         // floats per stage per operand
static constexpr int GSMEM = 4 * 2 * STAGE_F * 4; // 81920 bytes

__device__ __forceinline__ void load_tile(
    const float* __restrict__ A, int lda, int rowBase,
    const float* __restrict__ Bt, int ldb, int colBase,
    int k0, float* as, float* bs, int tid)
{
#pragma unroll
    for (int i = 0; i < 2; i++) {
        int idx = i * 256 + tid;
        int r = idx >> 2, c = (idx & 3) << 2;
        CP_ASYNC16(smem_u32(as + r * LDT + c), A + (size_t)(rowBase + r) * lda + k0 + c);
    }
#pragma unroll
    for (int i = 0; i < 2; i++) {
        int idx = i * 256 + tid;
        int r = idx >> 2, c = (idx & 3) << 2;
        CP_ASYNC16(smem_u32(bs + r * LDT + c), Bt + (size_t)(colBase + r) * ldb + k0 + c);
    }
    CP_COMMIT();
}

template <int EPI>
__global__ void __launch_bounds__(256, 2) tgemm(
    const float* __restrict__ A, int lda,
    const float* __restrict__ Bt, int ldb,
    const float* __restrict__ bias,
    float* __restrict__ C, int ldc,
    int Ntrue, int Nstore, int K,
    const float* __restrict__ X, int ldx)
{
    extern __shared__ float smem[];
    float* As = smem;                // 4 stages
    float* Bs = smem + 4 * STAGE_F;

    const int tid = threadIdx.x;
    const int wid = tid >> 5, lane = tid & 31;
    const int g = lane >> 2, tig = lane & 3;
    const int warp_m = wid & 1, warp_n = wid >> 1;
    const int rowBase = blockIdx.y * 128;
    const int colBase = blockIdx.x * 128;
    const int S = K >> 4;

    float acc[4][4][4];
#pragma unroll
    for (int mt = 0; mt < 4; mt++)
#pragma unroll
        for (int nt = 0; nt < 4; nt++)
#pragma unroll
            for (int q = 0; q < 4; q++) acc[mt][nt][q] = 0.f;

    load_tile(A, lda, rowBase, Bt, ldb, colBase, 0, As, Bs, tid);
    load_tile(A, lda, rowBase, Bt, ldb, colBase, 16, As + STAGE_F, Bs + STAGE_F, tid);
    load_tile(A, lda, rowBase, Bt, ldb, colBase, 32, As + 2 * STAGE_F, Bs + 2 * STAGE_F, tid);

    for (int s = 0; s < S; s++) {
        const int st = s & 3;
        if (s + 2 < S)      asm volatile("cp.async.wait_group 2;" ::: "memory");
        else if (s + 1 < S) asm volatile("cp.async.wait_group 1;" ::: "memory");
        else                asm volatile("cp.async.wait_group 0;" ::: "memory");
        __syncthreads();

        const float* aw = As + st * STAGE_F + (warp_m * 64 + g) * LDT + tig;
        const float* bw = Bs + st * STAGE_F + (warp_n * 32 + g) * LDT + tig;
#pragma unroll
        for (int kk = 0; kk < 16; kk += 8) {
            uint32_t af[4][4];
#pragma unroll
            for (int mt = 0; mt < 4; mt++) {
                const float* p = aw + mt * 16 * LDT + kk;
                af[mt][0] = ld_rna(p);
                af[mt][1] = ld_rna(p + 8 * LDT);
                af[mt][2] = ld_rna(p + 4);
                af[mt][3] = ld_rna(p + 8 * LDT + 4);
            }
            uint32_t bf[4][2];
#pragma unroll
            for (int nt = 0; nt < 4; nt++) {
                const float* p = bw + nt * 8 * LDT + kk;
                bf[nt][0] = ld_rna(p);
                bf[nt][1] = ld_rna(p + 4);
            }
#pragma unroll
            for (int mt = 0; mt < 4; mt++)
#pragma unroll
                for (int nt = 0; nt < 4; nt++)
                    mma_tf32(acc[mt][nt][0], acc[mt][nt][1], acc[mt][nt][2], acc[mt][nt][3],
                             af[mt][0], af[mt][1], af[mt][2], af[mt][3],
                             bf[nt][0], bf[nt][1]);
        }
        if (s + 3 < S)  // writes stage (s+3)&3 == (s-1)&3, consumed at s-1, safe after sync
            load_tile(A, lda, rowBase, Bt, ldb, colBase, (s + 3) * 16,
                      As + ((s + 3) & 3) * STAGE_F, Bs + ((s + 3) & 3) * STAGE_F, tid);
    }

    // ---- epilogue: direct stores ------------------------------------------
#pragma unroll
    for (int mt = 0; mt < 4; mt++) {
#pragma unroll
        for (int nt = 0; nt < 4; nt++) {
            int col = colBase + warp_n * 32 + nt * 8 + 2 * tig;
#pragma unroll
            for (int half = 0; half < 2; half++) {
                int row = rowBase + warp_m * 64 + mt * 16 + g + half * 8;
                float v0 = acc[mt][nt][half * 2 + 0];
                float v1 = acc[mt][nt][half * 2 + 1];
#pragma unroll
                for (int q = 0; q < 2; q++) {
                    int cc = col + q;
                    if (cc >= Nstore) continue;
                    float v = 0.f;
                    if (cc < Ntrue) {
                        v = (q ? v1 : v0) + bias[cc];
                        if (EPI == 1) v = fmaxf(v, 0.f);
                        if (EPI == 2) {
                            float sg = 1.f / (1.f + expf(-v));
                            v = X[(size_t)row * ldx + cc] * sg;
                        }
                    }
                    C[(size_t)row * ldc + cc] = v;
                }
            }
        }
    }
}

// ---------------- transpose weights ------------------------------------------
__global__ void __launch_bounds__(256) transposeW(
    const float* __restrict__ W, float* __restrict__ WT,
    int K, int N, int Kpad, int Npad)
{
    __shared__ float t[32][33];
    int kb = blockIdx.x * 32, nb = blockIdx.y * 32;
#pragma unroll
    for (int i = 0; i < 4; i++) {
        int kk = kb + threadIdx.y + i * 8, nn = nb + threadIdx.x;
        t[threadIdx.y + i * 8][threadIdx.x] = (kk < K && nn < N) ? W[(size_t)kk * N + nn] : 0.f;
    }
    __syncthreads();
#pragma unroll
    for (int i = 0; i < 4; i++) {
        int nn = nb + threadIdx.y + i * 8, kk = kb + threadIdx.x;
        if (nn < Npad && kk < Kpad)
            WT[(size_t)nn * Kpad + kk] = t[threadIdx.x][threadIdx.y + i * 8];
    }
}

// ---------------- per-row fusion --------------------------------------------
__global__ __launch_bounds__(256) void rowfuse(
    const float* __restrict__ E, const float* __restrict__ wgW,
    const float* __restrict__ wgb,
    float* __restrict__ common, float* __restrict__ cat)
{
    __shared__ float sE[3072];
    __shared__ float sred[8][9];
    __shared__ float sc[10];

    const int b = blockIdx.x;
    const int tid = threadIdx.x;
    const float* Erow = E + (size_t)b * 3072;
    for (int i = tid; i < 3072; i += 256) sE[i] = Erow[i];
    __syncthreads();

    float r[9] = {0, 0, 0, 0, 0, 0, 0, 0, 0};
    for (int h = tid; h < 1024; h += 256) {
        float e0 = sE[h], e1 = sE[1024 + h], e2 = sE[2048 + h];
        r[0] += e0 * e0; r[1] += e1 * e1; r[2] += e2 * e2;
        r[3] += e0 * e1; r[4] += e0 * e2; r[5] += e1 * e2;
    }
    for (int j = tid; j < 3072; j += 256) {
        float v = sE[j];
        r[6] += v * wgW[3 * j + 0];
        r[7] += v * wgW[3 * j + 1];
        r[8] += v * wgW[3 * j + 2];
    }
#pragma unroll
    for (int q = 0; q < 9; q++)
#pragma unroll
        for (int o = 16; o > 0; o >>= 1) r[q] += __shfl_down_sync(0xffffffffu, r[q], o);

    int warp = tid >> 5, lane = tid & 31;
    if (lane == 0)
        for (int q = 0; q < 9; q++) sred[warp][q] = r[q];
    __syncthreads();

    if (tid == 0) {
        float s[9];
        for (int q = 0; q < 9; q++) {
            float a = 0.f;
            for (int w2 = 0; w2 < 8; w2++) a += sred[w2][q];
            s[q] = a;
        }
        float inv0 = 1.f / fmaxf(sqrtf(s[0]), 1e-12f);
        float inv1 = 1.f / fmaxf(sqrtf(s[1]), 1e-12f);
        float inv2 = 1.f / fmaxf(sqrtf(s[2]), 1e-12f);
        float sim0 = s[3] * inv0 * inv1;
        float sim1 = s[4] * inv0 * inv2;
        float sim2 = s[5] * inv1 * inv2;
        bool k0 = sim0 > THRV, k1 = sim1 > THRV, k2 = sim2 > THRV;
        float x0 = k0 ? sim0 : -1e9f;
        float x1 = k1 ? sim1 : -1e9f;
        float x2 = k2 ? sim2 : -1e9f;
        float mx = fmaxf(x0, fmaxf(x1, x2));
        float ex0 = expf(x0 - mx), ex1 = expf(x1 - mx), ex2 = expf(x2 - mx);
        float es = ex0 + ex1 + ex2;
        float l0 = s[6] + wgb[0], l1 = s[7] + wgb[1], l2 = s[8] + wgb[2];
        float lm = fmaxf(l0, fmaxf(l1, l2));
        float g0 = expf(l0 - lm), g1 = expf(l1 - lm), g2 = expf(l2 - lm);
        float gs = g0 + g1 + g2;
        sc[0] = inv0; sc[1] = inv1; sc[2] = inv2;
        sc[3] = ex0 / es; sc[4] = ex1 / es; sc[5] = ex2 / es;
        sc[6] = g0 / gs; sc[7] = g1 / gs; sc[8] = g2 / gs;
        sc[9] = (k0 || k1 || k2) ? 1.f : 0.f;
    }
    __syncthreads();

    float inv0 = sc[0], inv1 = sc[1], inv2 = sc[2];
    float w0 = sc[3], w1 = sc[4], w2 = sc[5];
    float f0 = sc[6], f1 = sc[7], f2 = sc[8];
    bool any = sc[9] > 0.5f;
    float* crow = common + (size_t)b * 1024;
    float* catrow = cat + (size_t)b * 2048;
    for (int h = tid; h < 1024; h += 256) {
        float e0 = sE[h], e1 = sE[1024 + h], e2 = sE[2048 + h];
        float n0 = e0 * inv0, n1 = e1 * inv1, n2 = e2 * inv2;
        float wsum = 0.f;
        if (n0 * n1 > THRV) wsum += w0 * 0.5f * (e0 + e1);
        if (n0 * n2 > THRV) wsum += w1 * 0.5f * (e0 + e2);
        if (n1 * n2 > THRV) wsum += w2 * 0.5f * (e1 + e2);
        float mean = (e0 + e1 + e2) * (1.f / 3.f);
        crow[h] = any ? wsum : mean;
        catrow[h] = f0 * e0 + f1 * e1 + f2 * e2;
    }
}

// ---------------------------------------------------------------------------
extern "C" void kernel_launch(void* const* d_in, const int* in_sizes, int n_in,
                              void* d_out, int out_size)
{
    const float* xin[3] = {(const float*)d_in[0], (const float*)d_in[1], (const float*)d_in[2]};
    const float* w1[3]  = {(const float*)d_in[3], (const float*)d_in[7], (const float*)d_in[11]};
    const float* b1[3]  = {(const float*)d_in[4], (const float*)d_in[8], (const float*)d_in[12]};
    const float* w2[3]  = {(const float*)d_in[5], (const float*)d_in[9], (const float*)d_in[13]};
    const float* b2[3]  = {(const float*)d_in[6], (const float*)d_in[10], (const float*)d_in[14]};
    const float* wgW = (const float*)d_in[15]; const float* wgb = (const float*)d_in[16];
    const float* enhW = (const float*)d_in[17]; const float* enhb = (const float*)d_in[18];
    const float* fusW = (const float*)d_in[19]; const float* fusb = (const float*)d_in[20];
    float* out = (float*)d_out;

    float *H, *E, *C, *CAT, *WT1, *WT2, *ENT, *FUT;
    cudaGetSymbolAddress((void**)&H, g_H);
    cudaGetSymbolAddress((void**)&E, g_E);
    cudaGetSymbolAddress((void**)&C, g_C);
    cudaGetSymbolAddress((void**)&CAT, g_CAT);
    cudaGetSymbolAddress((void**)&WT1, g_WT1);
    cudaGetSymbolAddress((void**)&WT2, g_WT2);
    cudaGetSymbolAddress((void**)&ENT, g_enhT);
    cudaGetSymbolAddress((void**)&FUT, g_fusT);

    static bool attr_done = false;
    if (!attr_done) {
        cudaFuncSetAttribute(tgemm<0>, cudaFuncAttributeMaxDynamicSharedMemorySize, GSMEM);
        cudaFuncSetAttribute(tgemm<1>, cudaFuncAttributeMaxDynamicSharedMemorySize, GSMEM);
        cudaFuncSetAttribute(tgemm<2>, cudaFuncAttributeMaxDynamicSharedMemorySize, GSMEM);
        attr_done = true;
    }

    dim3 tb(32, 8);
    const int Mt = 16384 / 128;  // 128 M-tiles

    for (int br = 0; br < 3; br++) {
        // W1^T : [300->384 pad, 1024], W2^T : [1024, 300->320 pad]
        transposeW<<<dim3(32, 12), tb>>>(w1[br], WT1, 1024, 300, 1024, 384);
        transposeW<<<dim3(10, 32), tb>>>(w2[br], WT2, 300, 1024, 320, 1024);
        // H = relu(X @ W1 + b1)  (N=300 true, stored padded to 320 with zeros)
        tgemm<1><<<dim3(3, Mt), 256, GSMEM>>>(xin[br], 1024, WT1, 1024, b1[br],
                                              H, 320, 300, 320, 1024, nullptr, 0);
        // E[:, br, :] = H @ W2 + b2
        tgemm<0><<<dim3(8, Mt), 256, GSMEM>>>(H, 320, WT2, 320, b2[br],
                                              E + br * 1024, 3072, 1024, 1024, 320, nullptr, 0);
    }

    rowfuse<<<16384, 256>>>(E, wgW, wgb, C, CAT);

    transposeW<<<dim3(32, 32), tb>>>(enhW, ENT, 1024, 1024, 1024, 1024);
    tgemm<2><<<dim3(8, Mt), 256, GSMEM>>>(C, 1024, ENT, 1024, enhb,
                                          CAT + 1024, 2048, 1024, 1024, 1024, C, 1024);

    transposeW<<<dim3(64, 32), tb>>>(fusW, FUT, 2048, 1024, 2048, 1024);
    tgemm<0><<<dim3(8, Mt), 256, GSMEM>>>(CAT, 2048, FUT, 2048, fusb,
                                          out, 1024, 1024, 1024, 2048, nullptr, 0);
}

// round 5
// speedup vs baseline: 3.4985x; 1.1563x over previous
#include <cuda_runtime.h>
#include <math.h>
#include <stdint.h>

#define THRV 0.6f

// ---------------- scratch (device globals: no runtime allocation) ----------
__device__ float g_H[16384 * 320];        // MLP hidden (padded N/K=320), reused
__device__ float g_E[16384 * 3072];       // [B][3][1024]
__device__ float g_C[16384 * 1024];       // common
__device__ float g_CAT[16384 * 2048];     // [weighted_fp_sum | enhanced_common]
__device__ float g_WT1[384 * 1024];       // W1^T padded, tf32-rounded
__device__ float g_WT2[1024 * 320];       // W2^T padded, tf32-rounded
__device__ float g_enhT[1024 * 1024];
__device__ float g_fusT[1024 * 2048];

// ---------------- helpers ----------------------------------------------------
__device__ __forceinline__ uint32_t smem_u32(const void* p) {
    uint32_t a;
    asm("{ .reg .u64 t; cvta.to.shared.u64 t, %1; cvt.u32.u64 %0, t; }" : "=r"(a) : "l"(p));
    return a;
}
__device__ __forceinline__ float rna_tf32(float x) {
    uint32_t u;
    asm("cvt.rna.tf32.f32 %0, %1;" : "=r"(u) : "f"(x));
    return __uint_as_float(u);
}
__device__ __forceinline__ uint32_t rna_bits(uint32_t raw) {
    uint32_t u;
    asm("cvt.rna.tf32.f32 %0, %1;" : "=r"(u) : "f"(__uint_as_float(raw)));
    return u;
}
#define CP_ASYNC16(dst, src) asm volatile("cp.async.cg.shared.global [%0], [%1], 16;" :: "r"(dst), "l"(src))
#define CP_COMMIT()          asm volatile("cp.async.commit_group;" ::: "memory")

__device__ __forceinline__ void ldsm4(uint32_t& r0, uint32_t& r1, uint32_t& r2, uint32_t& r3,
                                      uint32_t addr) {
    asm volatile("ldmatrix.sync.aligned.m8n8.x4.shared.b16 {%0,%1,%2,%3}, [%4];"
                 : "=r"(r0), "=r"(r1), "=r"(r2), "=r"(r3) : "r"(addr));
}
__device__ __forceinline__ void mma_tf32(
    float& c0, float& c1, float& c2, float& c3,
    uint32_t a0, uint32_t a1, uint32_t a2, uint32_t a3,
    uint32_t b0, uint32_t b1)
{
    asm volatile(
        "mma.sync.aligned.m16n8k8.row.col.f32.tf32.tf32.f32 "
        "{%0,%1,%2,%3}, {%4,%5,%6,%7}, {%8,%9}, {%0,%1,%2,%3};"
        : "+f"(c0), "+f"(c1), "+f"(c2), "+f"(c3)
        : "r"(a0), "r"(a1), "r"(a2), "r"(a3), "r"(b0), "r"(b1));
}

// ---------------- tf32 tensor-core GEMM --------------------------------------
// C[M,N] = epi(A[M,K] @ Bt[N,K]^T + bias).  A row-major, Bt row-major (=W^T).
// BM=128, BN=128, BK=16, 256 thr, 8 warps (2m x 4n), warp tile 64x32.
// 4-stage cp.async pipeline; ldmatrix.x4 fragment loads.
// RA: round A frags in-register (for raw-input layer). RS: round stores.
// EPI 0: bias; 1: relu(bias); 2: X*sigmoid(bias).
static constexpr int LDT = 20;                    // conflict-free smem stride
static constexpr int STAGE_F = 128 * LDT;         // floats per stage per operand
static constexpr int GSMEM = 4 * 2 * STAGE_F * 4; // 81920 bytes

__device__ __forceinline__ void load_tile(
    const float* __restrict__ A, int lda, int rowBase,
    const float* __restrict__ Bt, int ldb, int colBase,
    int k0, float* as, float* bs, int tid)
{
#pragma unroll
    for (int i = 0; i < 2; i++) {
        int idx = i * 256 + tid;
        int r = idx >> 2, c = (idx & 3) << 2;
        CP_ASYNC16(smem_u32(as + r * LDT + c), A + (size_t)(rowBase + r) * lda + k0 + c);
    }
#pragma unroll
    for (int i = 0; i < 2; i++) {
        int idx = i * 256 + tid;
        int r = idx >> 2, c = (idx & 3) << 2;
        CP_ASYNC16(smem_u32(bs + r * LDT + c), Bt + (size_t)(colBase + r) * ldb + k0 + c);
    }
    CP_COMMIT();
}

template <int EPI, bool RA, bool RS>
__global__ void __launch_bounds__(256, 2) tgemm(
    const float* __restrict__ A, int lda,
    const float* __restrict__ Bt, int ldb,
    const float* __restrict__ bias,
    float* __restrict__ C, int ldc,
    int Ntrue, int Nstore, int K,
    const float* __restrict__ X, int ldx)
{
    extern __shared__ float smem[];
    float* As = smem;                // 4 stages
    float* Bs = smem + 4 * STAGE_F;

    const int tid = threadIdx.x;
    const int wid = tid >> 5, lane = tid & 31;
    const int g = lane >> 2, tig = lane & 3;
    const int warp_m = wid & 1, warp_n = wid >> 1;
    const int rowBase = blockIdx.y * 128;
    const int colBase = blockIdx.x * 128;
    const int S = K >> 4;

    // ldmatrix source addresses (per-thread rows of 16B)
    const int arow = (warp_m * 64 + (lane & 15)) * LDT + (lane >> 4) * 4;
    const int brow = (warp_n * 32 + (lane & 7) + ((lane & 16) ? 8 : 0)) * LDT
                   + ((lane & 8) ? 4 : 0);
    const uint32_t aBase = smem_u32(As) + arow * 4;
    const uint32_t bBase = smem_u32(Bs) + brow * 4;

    float acc[4][4][4];
#pragma unroll
    for (int mt = 0; mt < 4; mt++)
#pragma unroll
        for (int nt = 0; nt < 4; nt++)
#pragma unroll
            for (int q = 0; q < 4; q++) acc[mt][nt][q] = 0.f;

    load_tile(A, lda, rowBase, Bt, ldb, colBase, 0, As, Bs, tid);
    load_tile(A, lda, rowBase, Bt, ldb, colBase, 16, As + STAGE_F, Bs + STAGE_F, tid);
    load_tile(A, lda, rowBase, Bt, ldb, colBase, 32, As + 2 * STAGE_F, Bs + 2 * STAGE_F, tid);

    for (int s = 0; s < S; s++) {
        const int st = s & 3;
        if (s + 2 < S)      asm volatile("cp.async.wait_group 2;" ::: "memory");
        else if (s + 1 < S) asm volatile("cp.async.wait_group 1;" ::: "memory");
        else                asm volatile("cp.async.wait_group 0;" ::: "memory");
        __syncthreads();

        const uint32_t aSt = aBase + st * (STAGE_F * 4);
        const uint32_t bSt = bBase + st * (STAGE_F * 4);
#pragma unroll
        for (int kk = 0; kk < 16; kk += 8) {
            uint32_t af[4][4];
#pragma unroll
            for (int mt = 0; mt < 4; mt++) {
                ldsm4(af[mt][0], af[mt][1], af[mt][2], af[mt][3],
                      aSt + (mt * 16 * LDT + kk) * 4);
            }
            if (RA) {
#pragma unroll
                for (int mt = 0; mt < 4; mt++)
#pragma unroll
                    for (int q = 0; q < 4; q++) af[mt][q] = rna_bits(af[mt][q]);
            }
            uint32_t bf[4][2];
#pragma unroll
            for (int j = 0; j < 2; j++) {
                ldsm4(bf[2 * j][0], bf[2 * j][1], bf[2 * j + 1][0], bf[2 * j + 1][1],
                      bSt + (j * 16 * LDT + kk) * 4);
            }
#pragma unroll
            for (int mt = 0; mt < 4; mt++)
#pragma unroll
                for (int nt = 0; nt < 4; nt++)
                    mma_tf32(acc[mt][nt][0], acc[mt][nt][1], acc[mt][nt][2], acc[mt][nt][3],
                             af[mt][0], af[mt][1], af[mt][2], af[mt][3],
                             bf[nt][0], bf[nt][1]);
        }
        if (s + 3 < S)  // writes stage consumed at s-1, safe after this slice's sync
            load_tile(A, lda, rowBase, Bt, ldb, colBase, (s + 3) * 16,
                      As + ((s + 3) & 3) * STAGE_F, Bs + ((s + 3) & 3) * STAGE_F, tid);
    }

    // ---- epilogue: float2 stores ------------------------------------------
#pragma unroll
    for (int mt = 0; mt < 4; mt++) {
#pragma unroll
        for (int nt = 0; nt < 4; nt++) {
            int col = colBase + warp_n * 32 + nt * 8 + 2 * tig;
            if (col >= Nstore) continue;
#pragma unroll
            for (int half = 0; half < 2; half++) {
                int row = rowBase + warp_m * 64 + mt * 16 + g + half * 8;
                float v0 = 0.f, v1 = 0.f;
                if (col < Ntrue) {
                    v0 = acc[mt][nt][half * 2 + 0] + bias[col];
                    if (EPI == 1) v0 = fmaxf(v0, 0.f);
                    if (EPI == 2) v0 = X[(size_t)row * ldx + col] / (1.f + expf(-v0));
                    if (RS) v0 = rna_tf32(v0);
                }
                if (col + 1 < Ntrue) {
                    v1 = acc[mt][nt][half * 2 + 1] + bias[col + 1];
                    if (EPI == 1) v1 = fmaxf(v1, 0.f);
                    if (EPI == 2) v1 = X[(size_t)row * ldx + col + 1] / (1.f + expf(-v1));
                    if (RS) v1 = rna_tf32(v1);
                }
                *reinterpret_cast<float2*>(&C[(size_t)row * ldc + col]) = make_float2(v0, v1);
            }
        }
    }
}

// ---------------- transpose + tf32-round weights ----------------------------
__global__ void __launch_bounds__(256) transposeW(
    const float* __restrict__ W, float* __restrict__ WT,
    int K, int N, int Kpad, int Npad)
{
    __shared__ float t[32][33];
    int kb = blockIdx.x * 32, nb = blockIdx.y * 32;
#pragma unroll
    for (int i = 0; i < 4; i++) {
        int kk = kb + threadIdx.y + i * 8, nn = nb + threadIdx.x;
        t[threadIdx.y + i * 8][threadIdx.x] = (kk < K && nn < N) ? W[(size_t)kk * N + nn] : 0.f;
    }
    __syncthreads();
#pragma unroll
    for (int i = 0; i < 4; i++) {
        int nn = nb + threadIdx.y + i * 8, kk = kb + threadIdx.x;
        if (nn < Npad && kk < Kpad)
            WT[(size_t)nn * Kpad + kk] = rna_tf32(t[threadIdx.x][threadIdx.y + i * 8]);
    }
}

// ---------------- per-row fusion --------------------------------------------
__global__ __launch_bounds__(256) void rowfuse(
    const float* __restrict__ E, const float* __restrict__ wgW,
    const float* __restrict__ wgb,
    float* __restrict__ common, float* __restrict__ cat)
{
    __shared__ float sE[3072];
    __shared__ float sred[8][9];
    __shared__ float sc[10];

    const int b = blockIdx.x;
    const int tid = threadIdx.x;
    const float* Erow = E + (size_t)b * 3072;
    for (int i = tid; i < 3072; i += 256) sE[i] = Erow[i];
    __syncthreads();

    float r[9] = {0, 0, 0, 0, 0, 0, 0, 0, 0};
    for (int h = tid; h < 1024; h += 256) {
        float e0 = sE[h], e1 = sE[1024 + h], e2 = sE[2048 + h];
        r[0] += e0 * e0; r[1] += e1 * e1; r[2] += e2 * e2;
        r[3] += e0 * e1; r[4] += e0 * e2; r[5] += e1 * e2;
    }
    for (int j = tid; j < 3072; j += 256) {
        float v = sE[j];
        r[6] += v * wgW[3 * j + 0];
        r[7] += v * wgW[3 * j + 1];
        r[8] += v * wgW[3 * j + 2];
    }
#pragma unroll
    for (int q = 0; q < 9; q++)
#pragma unroll
        for (int o = 16; o > 0; o >>= 1) r[q] += __shfl_down_sync(0xffffffffu, r[q], o);

    int warp = tid >> 5, lane = tid & 31;
    if (lane == 0)
        for (int q = 0; q < 9; q++) sred[warp][q] = r[q];
    __syncthreads();

    if (tid == 0) {
        float s[9];
        for (int q = 0; q < 9; q++) {
            float a = 0.f;
            for (int w2 = 0; w2 < 8; w2++) a += sred[w2][q];
            s[q] = a;
        }
        float inv0 = 1.f / fmaxf(sqrtf(s[0]), 1e-12f);
        float inv1 = 1.f / fmaxf(sqrtf(s[1]), 1e-12f);
        float inv2 = 1.f / fmaxf(sqrtf(s[2]), 1e-12f);
        float sim0 = s[3] * inv0 * inv1;
        float sim1 = s[4] * inv0 * inv2;
        float sim2 = s[5] * inv1 * inv2;
        bool k0 = sim0 > THRV, k1 = sim1 > THRV, k2 = sim2 > THRV;
        float x0 = k0 ? sim0 : -1e9f;
        float x1 = k1 ? sim1 : -1e9f;
        float x2 = k2 ? sim2 : -1e9f;
        float mx = fmaxf(x0, fmaxf(x1, x2));
        float ex0 = expf(x0 - mx), ex1 = expf(x1 - mx), ex2 = expf(x2 - mx);
        float es = ex0 + ex1 + ex2;
        float l0 = s[6] + wgb[0], l1 = s[7] + wgb[1], l2 = s[8] + wgb[2];
        float lm = fmaxf(l0, fmaxf(l1, l2));
        float g0 = expf(l0 - lm), g1 = expf(l1 - lm), g2 = expf(l2 - lm);
        float gs = g0 + g1 + g2;
        sc[0] = inv0; sc[1] = inv1; sc[2] = inv2;
        sc[3] = ex0 / es; sc[4] = ex1 / es; sc[5] = ex2 / es;
        sc[6] = g0 / gs; sc[7] = g1 / gs; sc[8] = g2 / gs;
        sc[9] = (k0 || k1 || k2) ? 1.f : 0.f;
    }
    __syncthreads();

    float inv0 = sc[0], inv1 = sc[1], inv2 = sc[2];
    float w0 = sc[3], w1 = sc[4], w2 = sc[5];
    float f0 = sc[6], f1 = sc[7], f2 = sc[8];
    bool any = sc[9] > 0.5f;
    float* crow = common + (size_t)b * 1024;
    float* catrow = cat + (size_t)b * 2048;
    for (int h = tid; h < 1024; h += 256) {
        float e0 = sE[h], e1 = sE[1024 + h], e2 = sE[2048 + h];
        float n0 = e0 * inv0, n1 = e1 * inv1, n2 = e2 * inv2;
        float wsum = 0.f;
        if (n0 * n1 > THRV) wsum += w0 * 0.5f * (e0 + e1);
        if (n0 * n2 > THRV) wsum += w1 * 0.5f * (e0 + e2);
        if (n1 * n2 > THRV) wsum += w2 * 0.5f * (e1 + e2);
        float mean = (e0 + e1 + e2) * (1.f / 3.f);
        crow[h] = rna_tf32(any ? wsum : mean);           // consumed as GEMM A
        catrow[h] = rna_tf32(f0 * e0 + f1 * e1 + f2 * e2); // consumed as GEMM A
    }
}

// ---------------------------------------------------------------------------
extern "C" void kernel_launch(void* const* d_in, const int* in_sizes, int n_in,
                              void* d_out, int out_size)
{
    const float* xin[3] = {(const float*)d_in[0], (const float*)d_in[1], (const float*)d_in[2]};
    const float* w1[3]  = {(const float*)d_in[3], (const float*)d_in[7], (const float*)d_in[11]};
    const float* b1[3]  = {(const float*)d_in[4], (const float*)d_in[8], (const float*)d_in[12]};
    const float* w2[3]  = {(const float*)d_in[5], (const float*)d_in[9], (const float*)d_in[13]};
    const float* b2[3]  = {(const float*)d_in[6], (const float*)d_in[10], (const float*)d_in[14]};
    const float* wgW = (const float*)d_in[15]; const float* wgb = (const float*)d_in[16];
    const float* enhW = (const float*)d_in[17]; const float* enhb = (const float*)d_in[18];
    const float* fusW = (const float*)d_in[19]; const float* fusb = (const float*)d_in[20];
    float* out = (float*)d_out;

    float *H, *E, *C, *CAT, *WT1, *WT2, *ENT, *FUT;
    cudaGetSymbolAddress((void**)&H, g_H);
    cudaGetSymbolAddress((void**)&E, g_E);
    cudaGetSymbolAddress((void**)&C, g_C);
    cudaGetSymbolAddress((void**)&CAT, g_CAT);
    cudaGetSymbolAddress((void**)&WT1, g_WT1);
    cudaGetSymbolAddress((void**)&WT2, g_WT2);
    cudaGetSymbolAddress((void**)&ENT, g_enhT);
    cudaGetSymbolAddress((void**)&FUT, g_fusT);

    static bool attr_done = false;
    if (!attr_done) {
        cudaFuncSetAttribute((const void*)tgemm<1, true, true>,  cudaFuncAttributeMaxDynamicSharedMemorySize, GSMEM);
        cudaFuncSetAttribute((const void*)tgemm<0, false, false>, cudaFuncAttributeMaxDynamicSharedMemorySize, GSMEM);
        cudaFuncSetAttribute((const void*)tgemm<2, false, true>, cudaFuncAttributeMaxDynamicSharedMemorySize, GSMEM);
        attr_done = true;
    }

    dim3 tb(32, 8);
    const int Mt = 16384 / 128;  // 128 M-tiles

    for (int br = 0; br < 3; br++) {
        // W1^T : [300->384 pad, 1024], W2^T : [1024, 300->320 pad] (tf32-rounded)
        transposeW<<<dim3(32, 12), tb>>>(w1[br], WT1, 1024, 300, 1024, 384);
        transposeW<<<dim3(10, 32), tb>>>(w2[br], WT2, 300, 1024, 320, 1024);
        // H = relu(X @ W1 + b1): A raw -> RA, stores feed next GEMM -> RS
        tgemm<1, true, true><<<dim3(3, Mt), 256, GSMEM>>>(
            xin[br], 1024, WT1, 1024, b1[br], H, 320, 300, 320, 1024, nullptr, 0);
        // E[:, br, :] = H @ W2 + b2: A pre-rounded; E feeds rowfuse only
        tgemm<0, false, false><<<dim3(8, Mt), 256, GSMEM>>>(
            H, 320, WT2, 320, b2[br], E + br * 1024, 3072, 1024, 1024, 320, nullptr, 0);
    }

    rowfuse<<<16384, 256>>>(E, wgW, wgb, C, CAT);

    transposeW<<<dim3(32, 32), tb>>>(enhW, ENT, 1024, 1024, 1024, 1024);
    // CAT[:,1024:] = C * sigmoid(C @ enhW + enhb); feeds fused GEMM -> RS
    tgemm<2, false, true><<<dim3(8, Mt), 256, GSMEM>>>(
        C, 1024, ENT, 1024, enhb, CAT + 1024, 2048, 1024, 1024, 1024, C, 1024);

    transposeW<<<dim3(64, 32), tb>>>(fusW, FUT, 2048, 1024, 2048, 1024);
    // final output: no store rounding
    tgemm<0, false, false><<<dim3(8, Mt), 256, GSMEM>>>(
        CAT, 2048, FUT, 2048, fusb, out, 1024, 1024, 1024, 2048, nullptr, 0);
}